// round 1
// baseline (speedup 1.0000x reference)
#include <cuda_runtime.h>
#include <stdint.h>

// Problem constants (fixed shapes from reference)
#define DET       1024
#define REPS      3
#define T_TOT     (DET * REPS)       // 3072
#define NSTATES   64
#define BATCH     256
#define CLAMP_V   50.0f
#define SOFT_T    1025               // time steps 1023..2047 inclusive
#define SOFT_ROW  (SOFT_T * NSTATES) // 65600 floats per batch

// Survivor bits, packed: word.x bit l = ind[state 2l], word.y bit l = ind[state 2l+1].
// Only needed for t in [1024, 3072)  -> index t-1024. 256*2048*8B = 4 MB.
__device__ uint2 g_prev[BATCH * 2048];

// ---------------------------------------------------------------------------
// Forward ACS: one warp per batch. Lane l holds states 2l (a) and 2l+1 (b).
// Predecessors of both states are {l, l+32}: 4 shuffles per step.
// ---------------------------------------------------------------------------
__global__ void __launch_bounds__(32, 1)
viterbi_fwd(const float* __restrict__ x, const float* __restrict__ w,
            float* __restrict__ soft)
{
    const int b    = blockIdx.x;
    const int lane = threadIdx.x;

    const float2* __restrict__ xrow = reinterpret_cast<const float2*>(x + (size_t)b * (DET * 2));
    float2* __restrict__ softrow =
        reinterpret_cast<float2*>(soft + (size_t)b * SOFT_ROW) + lane;
    uint2* __restrict__ prevrow = g_prev + (size_t)b * 2048;

    // --- per-lane edge sign codes ---------------------------------------
    // For new state n, edge e: prev p = (n>>1) + 32e.  For lane l: p = l + 32e.
    // c0 = b ^ p1 ^ p2 ^ p4 ^ p5 ;  c1 = b ^ p0 ^ p1 ^ p2 ^ p5  (b = n&1)
    // bm = (1-2c0)*llr0 + (1-2c1)*llr1 = sgn * (c0^c1 ? (llr0-llr1) : (llr0+llr1))
    // Odd state (n=2l+1) flips b -> flips both c's -> bm negated, selector same.
    float sgn0, sgn1;
    int   dif0, dif1;
    {
        int p  = lane;                               // edge 0
        int c0 = ((p >> 1) ^ (p >> 2) ^ (p >> 4) ^ (p >> 5)) & 1;
        int c1 = (p ^ (p >> 1) ^ (p >> 2) ^ (p >> 5)) & 1;
        sgn0 = c0 ? -1.0f : 1.0f;  dif0 = c0 ^ c1;
        p  = lane + 32;                              // edge 1
        c0 = ((p >> 1) ^ (p >> 2) ^ (p >> 4) ^ (p >> 5)) & 1;
        c1 = (p ^ (p >> 1) ^ (p >> 2) ^ (p >> 5)) & 1;
        sgn1 = c0 ? -1.0f : 1.0f;  dif1 = c0 ^ c1;
    }
    const int  srcLo = lane >> 1;         // holds prob[lane]
    const int  srcHi = 16 + (lane >> 1);  // holds prob[lane+32]
    const bool odd   = (lane & 1) != 0;

    // initial metrics: state 0 = +50, rest 0
    float a  = (lane == 0) ? CLAMP_V : 0.0f;  // state 2*lane
    float bq = 0.0f;                          // state 2*lane + 1

    // prefetch step 0 inputs
    float2 ll = xrow[0];
    float  wt = w[0];

    for (int t = 0; t < T_TOT; t++) {
        // ---- prefetch next step's inputs (independent of the chain) ----
        float2 lln = ll;
        float  wn  = wt;
        int tn = t + 1;
        if (tn < T_TOT) {
            lln = xrow[tn & (DET - 1)];
            wn  = __ldg(w + tn);
        }

        // ---- gather predecessor metrics (critical path) ----
        float ta = __shfl_sync(0xffffffffu, a,  srcLo);
        float tb = __shfl_sync(0xffffffffu, bq, srcLo);
        float ua = __shfl_sync(0xffffffffu, a,  srcHi);
        float ub = __shfl_sync(0xffffffffu, bq, srcHi);
        float pLo = odd ? tb : ta;   // prob[lane]
        float pHi = odd ? ub : ua;   // prob[lane+32]

        // ---- branch metrics (match reference rounding exactly) ----
        float wSum = wt * (ll.x + ll.y);
        float wDif = wt * (ll.x - ll.y);
        float wb0  = dif0 ? wDif : wSum;
        float wb1  = dif1 ? wDif : wSum;

        float c00 = fmaf( sgn0, wb0, pLo);   // state 2l,   edge 0
        float c01 = fmaf( sgn1, wb1, pHi);   // state 2l,   edge 1
        float c10 = fmaf(-sgn0, wb0, pLo);   // state 2l+1, edge 0
        float c11 = fmaf(-sgn1, wb1, pHi);   // state 2l+1, edge 1

        float na = fmaxf(c00, c01);
        float nb = fmaxf(c10, c11);
        bool  ia = c01 > c00;   // jnp.argmax: index 1 only on strict >
        bool  ib = c11 > c10;

        // ---- mean over 64 states (warp butterfly; exact *2^-6 scaling) ----
        float s = na + nb;
        s += __shfl_xor_sync(0xffffffffu, s, 1);
        s += __shfl_xor_sync(0xffffffffu, s, 2);
        s += __shfl_xor_sync(0xffffffffu, s, 4);
        s += __shfl_xor_sync(0xffffffffu, s, 8);
        s += __shfl_xor_sync(0xffffffffu, s, 16);
        float m = s * (1.0f / 64.0f);

        na = fminf(fmaxf(na - m, -CLAMP_V), CLAMP_V);
        nb = fminf(fmaxf(nb - m, -CLAMP_V), CLAMP_V);

        // ---- survivor bits (only needed for t >= 1024) ----
        unsigned ba = __ballot_sync(0xffffffffu, ia);
        unsigned bb = __ballot_sync(0xffffffffu, ib);
        if (t >= 1024 && lane == 0)
            prevrow[t - 1024] = make_uint2(ba, bb);

        // ---- soft output window: t in [1023, 2047] ----
        if (t >= 1023 && t < 2048)
            softrow[(t - 1023) * 32] = make_float2(na, nb);

        a  = na;  bq = nb;
        ll = lln; wt = wn;
    }
}

// ---------------------------------------------------------------------------
// Traceback: one thread per batch. Load addresses are state-independent, so
// loads pipeline under unrolling; only the bit-extract chain is serial.
// ---------------------------------------------------------------------------
__global__ void viterbi_tb(float* __restrict__ dec)
{
    int b = blockIdx.x * blockDim.x + threadIdx.x;
    if (b >= BATCH) return;

    const uint2* __restrict__ prevrow = g_prev + (size_t)b * 2048;
    float* __restrict__ drow = dec + (size_t)b * DET;

    int state = 0;  // state at t = T-1
#pragma unroll 8
    for (int t = T_TOT - 1; t >= 1024; t--) {
        uint2 wp = prevrow[t - 1024];
        int bit = 1 - (state & 1);           // (state+1) % 2
        if (t < 2048)
            drow[t - 1024] = (float)bit;
        unsigned wsel = (state & 1) ? wp.y : wp.x;
        int ind = (wsel >> (state >> 1)) & 1;
        state = (state >> 1) + (ind << 5);   // TRANS_PREV[state][ind]
    }
}

// ---------------------------------------------------------------------------
// Harness entry. Output layout: decoded_words (256*1024 f32) then soft
// (256*65600 f32), concatenated.
// ---------------------------------------------------------------------------
extern "C" void kernel_launch(void* const* d_in, const int* in_sizes, int n_in,
                              void* d_out, int out_size)
{
    const float* x  = (const float*)d_in[0];   // (256, 2048)
    const float* wv = (const float*)d_in[1];   // (3072,)
    float* out = (float*)d_out;

    float* dec  = out;                         // 256*1024
    float* soft = out + (size_t)BATCH * DET;   // 256*65600

    viterbi_fwd<<<BATCH, 32>>>(x, wv, soft);
    viterbi_tb<<<8, 32>>>(dec);
}